// round 14
// baseline (speedup 1.0000x reference)
#include <cuda_runtime.h>
#include <cstdint>
#include <cstddef>

#define NQ   25200
#define NB   16
#define NCLS 80
#define PC   85
#define TOPK 1024
#define MAXDET 300
#define CONF_THF 0.6f
#define IOU_THF  0.45f
#define MAX_WHF  4096.0f
#define CAND_CAP 2048
#define LISTCAP  16384
#define FULLM 0xffffffffu

// ---------------- scratch (device globals: no allocation allowed) ----------------
__device__ int      g_cls[NB * NQ];
__device__ unsigned long long g_list[NB * LISTCAP];
__device__ int      g_cnt[NB];                 // static-init zero; k2 resets after reading
__device__ int      g_selidx[NB * TOPK];
__device__ float    g_selscore[NB * TOPK];
__device__ int      g_selcls[NB * TOPK];
__device__ float    g_obox[NB * TOPK * 4];
__device__ float    g_area[NB * TOPK];
__device__ float    g_rawbox[NB * TOPK * 4];
__device__ unsigned g_mask[NB * TOPK * 32];
__device__ int      g_keep[NB * MAXDET];
__device__ int      g_nk[NB];

// ---------------- kernel 1: smem-staged score/argmax + valid-list append ----------------
#define K1B 99
#define K1_SMEM (256 * PC * 4)
__global__ void __launch_bounds__(256) k1_score(const float* __restrict__ pred) {
    extern __shared__ float s_row[];
    int tid = threadIdx.x;
    int lane = tid & 31;
    int img = blockIdx.y;
    int base = blockIdx.x * 256;
    int nA = NQ - base; if (nA > 256) nA = 256;
    int nVec = nA * PC / 4;
    const float4* gp4 = (const float4*)(pred + ((size_t)img * NQ + base) * PC);
    float4* sp4 = (float4*)s_row;
    for (int v = tid; v < nVec; v += 256) sp4[v] = __ldg(gp4 + v);
    __syncthreads();

    bool valid = false;
    unsigned ord = 0;
    if (tid < nA) {
        const float* row = s_row + tid * PC;
        float obj = row[4];
        float best = -1e30f;
        int bidx = 0;
        #pragma unroll 8
        for (int c = 0; c < NCLS; ++c) {
            float p = __fmul_rn(row[5 + c], obj);
            if (p > best) { best = p; bidx = c; }
        }
        valid = (obj > CONF_THF) && (best > CONF_THF);
        ord = __float_as_uint(best) | 0x80000000u;
        g_cls[img * NQ + base + tid] = bidx;
    }
    unsigned mm = __ballot_sync(FULLM, valid);
    if (mm) {
        int leader = __ffs(mm) - 1;
        int pos0 = 0;
        if (lane == leader) pos0 = atomicAdd(&g_cnt[img], __popc(mm));
        pos0 = __shfl_sync(FULLM, pos0, leader);
        if (valid) {
            int pos = pos0 + __popc(mm & ((1u << lane) - 1u));
            if (pos < LISTCAP)
                g_list[img * LISTCAP + pos] =
                    ((unsigned long long)ord << 32) | (unsigned)(base + tid);
        }
    }
}

// ---------------- kernel 2: list-based radix-select top-1024 + hybrid sort + gather ----------------
#define K2_SMEM (LISTCAP * 8 + CAND_CAP * 8)
#define K2_ROUNDS (LISTCAP / 1024)

__device__ __forceinline__ void wstage(unsigned long long& v, int lane, unsigned idx,
                                       unsigned kk2, unsigned jj) {
    unsigned long long o = __shfl_xor_sync(FULLM, v, jj);
    bool low = ((lane & jj) == 0);
    bool up  = ((idx & kk2) == 0);
    unsigned long long mn = (v < o) ? v : o;
    unsigned long long mx = (v < o) ? o : v;
    v = (low == up) ? mn : mx;
}

__global__ void __launch_bounds__(1024) k2_select(const float* __restrict__ pred) {
    extern __shared__ unsigned char k2smem[];
    unsigned long long* s_list = (unsigned long long*)k2smem;
    unsigned long long* s_key  = (unsigned long long*)(k2smem + LISTCAP * 8);

    __shared__ unsigned s_hist[256];
    __shared__ unsigned s_sel, s_kk;
    __shared__ int s_cnt;

    int img = blockIdx.x;
    int tid = threadIdx.x;
    int lane = tid & 31;

    int n = g_cnt[img];
    if (n > LISTCAP) n = LISTCAP;
    for (int i = tid; i < n; i += 1024) s_list[i] = g_list[img * LISTCAP + i];
    __syncthreads();                       // all threads have read g_cnt
    if (tid == 0) g_cnt[img] = 0;          // self-reset: replaces memset node

    unsigned T = 0;
    if (n > TOPK) {
        unsigned prefix = 0;
        int k = TOPK;
        for (int p = 0; p < 4; ++p) {
            int shift = 24 - 8 * p;
            unsigned fmask = (p == 0) ? 0u : (0xFFFFFFFFu << (32 - 8 * p));
            if (tid < 256) s_hist[tid] = 0;
            __syncthreads();
            #pragma unroll
            for (int r = 0; r < K2_ROUNDS; ++r) {
                int i = tid + (r << 10);
                bool act = i < n;
                unsigned o = act ? (unsigned)(s_list[i] >> 32) : 0u;
                bool in = act && (((o ^ prefix) & fmask) == 0);
                unsigned bin = (o >> shift) & 255u;
                unsigned mm = __ballot_sync(FULLM, in);
                if (in) {
                    unsigned same = __match_any_sync(mm, bin);
                    if ((__ffs(same) - 1) == lane)
                        atomicAdd(&s_hist[bin], __popc(same));
                }
            }
            __syncthreads();
            if (tid < 32) {
                unsigned c[8]; unsigned tot = 0;
                #pragma unroll
                for (int r = 0; r < 8; ++r) { c[r] = s_hist[tid * 8 + r]; tot += c[r]; }
                unsigned x = tot;
                #pragma unroll
                for (int off = 1; off < 32; off <<= 1) {
                    unsigned y = __shfl_down_sync(FULLM, x, off);
                    if (tid + off < 32) x += y;
                }
                unsigned acc = x - tot;
                #pragma unroll
                for (int r = 7; r >= 0; --r) {
                    unsigned inc = acc + c[r];
                    if ((int)inc >= k && (int)acc < k) { s_sel = (unsigned)(tid * 8 + r); s_kk = (unsigned)(k - (int)acc); }
                    acc = inc;
                }
            }
            __syncthreads();
            prefix |= s_sel << shift;
            k = (int)s_kk;
            __syncthreads();
        }
        T = prefix;
    }

    if (tid == 0) s_cnt = 0;
    __syncthreads();
    #pragma unroll
    for (int r = 0; r < K2_ROUNDS; ++r) {
        int i = tid + (r << 10);
        bool act = i < n;
        unsigned o = 0, idx = 0;
        if (act) {
            unsigned long long e = s_list[i];
            o = (unsigned)(e >> 32);
            idx = (unsigned)(e & 0xFFFFFFFFull);
        }
        bool take = act && (o >= T);
        unsigned mm = __ballot_sync(FULLM, take);
        if (mm) {
            int leader = __ffs(mm) - 1;
            int base = 0;
            if (lane == leader) base = atomicAdd(&s_cnt, __popc(mm));
            base = __shfl_sync(FULLM, base, leader);
            if (take) {
                int pos = base + __popc(mm & ((1u << lane) - 1u));
                if (pos < CAND_CAP)
                    s_key[pos] = ((unsigned long long)(~o) << 32) | idx;
            }
        }
    }
    __syncthreads();
    int nc = s_cnt; if (nc > CAND_CAP) nc = CAND_CAP;
    for (int i = nc + tid; i < CAND_CAP; i += 1024) s_key[i] = ~0ull;
    __syncthreads();

    {
        int W = tid >> 5;
        unsigned ia = W * 64 + lane;
        unsigned ib = W * 64 + 32 + lane;
        {
            unsigned long long a = s_key[ia], b = s_key[ib];
            #pragma unroll
            for (unsigned kk2 = 2; kk2 <= 32; kk2 <<= 1)
                #pragma unroll
                for (unsigned jj = kk2 >> 1; jj >= 1; jj >>= 1) {
                    wstage(a, lane, ia, kk2, jj);
                    wstage(b, lane, ib, kk2, jj);
                }
            s_key[ia] = a; s_key[ib] = b;
        }
        __syncthreads();
        for (unsigned kk2 = 64; kk2 <= CAND_CAP; kk2 <<= 1) {
            for (unsigned jj = kk2 >> 1; jj >= 32; jj >>= 1) {
                unsigned t = (unsigned)tid;
                unsigned e = ((t & ~(jj - 1)) << 1) | (t & (jj - 1));
                unsigned pi = e | jj;
                bool up = ((e & kk2) == 0);
                unsigned long long a = s_key[e], b2 = s_key[pi];
                bool sw = up ? (a > b2) : (a < b2);
                if (sw) { s_key[e] = b2; s_key[pi] = a; }
                __syncthreads();
            }
            unsigned long long a = s_key[ia], b = s_key[ib];
            #pragma unroll
            for (unsigned jj = 16; jj >= 1; jj >>= 1) {
                wstage(a, lane, ia, kk2, jj);
                wstage(b, lane, ib, kk2, jj);
            }
            s_key[ia] = a; s_key[ib] = b;
            __syncthreads();
        }
    }

    unsigned long long key = s_key[tid];
    int aidx; float scr; int cls;
    if ((key >> 32) == 0xFFFFFFFFull) {
        aidx = 0; scr = -1.0f; cls = 0;
    } else {
        aidx = (int)(unsigned)(key & 0xFFFFFFFFull);
        unsigned ordv = ~(unsigned)(key >> 32);
        scr  = __uint_as_float(ordv & 0x7FFFFFFFu);
        cls  = g_cls[img * NQ + aidx];
    }
    const float* row = pred + ((size_t)(img * NQ + aidx)) * PC;
    float cx = row[0], cy = row[1], w = row[2], h = row[3];
    float hw = __fmul_rn(w, 0.5f), hh = __fmul_rn(h, 0.5f);
    float x1 = __fsub_rn(cx, hw), y1 = __fsub_rn(cy, hh);
    float x2 = __fadd_rn(cx, hw), y2 = __fadd_rn(cy, hh);
    float off = __fmul_rn((float)cls, MAX_WHF);
    float ox1 = __fadd_rn(x1, off), oy1 = __fadd_rn(y1, off);
    float ox2 = __fadd_rn(x2, off), oy2 = __fadd_rn(y2, off);

    int gi = img * TOPK + tid;
    g_selidx[gi]   = aidx;
    g_selscore[gi] = scr;
    g_selcls[gi]   = cls;
    g_rawbox[gi*4+0] = x1; g_rawbox[gi*4+1] = y1; g_rawbox[gi*4+2] = x2; g_rawbox[gi*4+3] = y2;
    g_obox[gi*4+0] = ox1; g_obox[gi*4+1] = oy1; g_obox[gi*4+2] = ox2; g_obox[gi*4+3] = oy2;
    g_area[gi] = __fmul_rn(__fsub_rn(ox2, ox1), __fsub_rn(oy2, oy1));
}

// ---------------- kernel 3: IoU bitmask, warp-per-row, lane=j, div only if inter>0 ----------------
#define K3_BLKS 32

__global__ void __launch_bounds__(256) k3_mask() {
    int img = blockIdx.y;
    __shared__ float s_x1[TOPK], s_y1[TOPK], s_x2[TOPK], s_y2[TOPK], s_ar[TOPK];
    int tid = threadIdx.x;
    int wid = tid >> 5;
    int lane = tid & 31;
    for (int j = tid; j < TOPK; j += 256) {
        float4 b = ((const float4*)g_obox)[img * TOPK + j];
        s_x1[j] = b.x; s_y1[j] = b.y; s_x2[j] = b.z; s_y2[j] = b.w;
        s_ar[j] = g_area[img * TOPK + j];
    }
    __syncthreads();

    int g = blockIdx.x * 8 + wid;
    for (int rr = 0; rr < TOPK / (K3_BLKS * 8); ++rr) {
        int i = g + rr * (K3_BLKS * 8);
        float ax1 = s_x1[i], ay1 = s_y1[i], ax2 = s_x2[i], ay2 = s_y2[i], aar = s_ar[i];
        int w0 = i >> 5;
        unsigned* mrow = g_mask + (img * TOPK + i) * 32;
        if (lane < w0) mrow[lane] = 0;
        for (int w = w0; w < 32; ++w) {
            int j = w * 32 + lane;
            float xx1 = fmaxf(ax1, s_x1[j]);
            float yy1 = fmaxf(ay1, s_y1[j]);
            float xx2 = fminf(ax2, s_x2[j]);
            float yy2 = fminf(ay2, s_y2[j]);
            float iw = fmaxf(__fsub_rn(xx2, xx1), 0.0f);
            float ih = fmaxf(__fsub_rn(yy2, yy1), 0.0f);
            float inter = __fmul_rn(iw, ih);
            bool sup = false;
            if (j > i && inter > 0.0f) {
                float denom = __fadd_rn(__fsub_rn(__fadd_rn(aar, s_ar[j]), inter), 1e-9f);
                sup = __fdiv_rn(inter, denom) > IOU_THF;
            }
            unsigned bits = __ballot_sync(FULLM, sup);
            if (lane == 0) mrow[w] = bits;
        }
    }
}

// ---------------- kernel 4: single-warp resolve, mask read from L2 ----------------
__global__ void __launch_bounds__(32) k4_resolve() {
    int img = blockIdx.x;
    int lane = threadIdx.x;

    // lane l builds validity word l (scores L2-hot from k2)
    unsigned vw = 0;
    const float* sc = g_selscore + img * TOPK + lane * 32;
    #pragma unroll
    for (int b = 0; b < 32; ++b)
        vw |= (__ldg(sc + b) > CONF_THF ? 1u : 0u) << b;

    const unsigned* M = g_mask + (size_t)img * TOPK * 32;
    unsigned remv = 0;   // lane l holds suppression word l
    int nk = 0;
    unsigned above = (lane < 31) ? ~((2u << lane) - 1u) : 0u;
    for (int w = 0; w < 32 && nk < MAXDET; ++w) {
        unsigned cur = __shfl_sync(FULLM, vw, w) & ~__shfl_sync(FULLM, remv, w);
        unsigned kept = 0;
        if (cur) {
            unsigned diag = __ldg(M + (w * 32 + lane) * 32 + w);
            unsigned alive = cur;
            while (alive) {
                bool supp = ((alive >> lane) & 1u) && ((diag & alive & above) != 0u);
                unsigned sball = __ballot_sync(FULLM, supp);
                if (!sball) { kept |= alive; break; }
                int b = __ffs(sball) - 1;
                unsigned ble = (b < 31) ? ((2u << b) - 1u) : 0xFFFFFFFFu;
                unsigned batch = alive & ble;
                kept |= batch;
                alive &= ~batch;
                alive &= ~__shfl_sync(FULLM, diag, b);
            }
            int cnt = __popc(kept);
            int room = MAXDET - nk;
            while (cnt > room) { kept &= ~(1u << (31 - __clz(kept))); --cnt; }
            if ((kept >> lane) & 1u)
                g_keep[img * MAXDET + nk + __popc(kept & ((1u << lane) - 1u))] = w * 32 + lane;
            nk += cnt;
            if (kept) {
                const unsigned* base = M + (size_t)(w * 32) * 32 + lane;
                unsigned o0 = 0, o1 = 0, o2 = 0, o3 = 0;
                #pragma unroll
                for (int b = 0; b < 8; ++b) {
                    if (kept & (1u << (b * 4 + 0))) o0 |= __ldg(base + (b * 4 + 0) * 32);
                    if (kept & (1u << (b * 4 + 1))) o1 |= __ldg(base + (b * 4 + 1) * 32);
                    if (kept & (1u << (b * 4 + 2))) o2 |= __ldg(base + (b * 4 + 2) * 32);
                    if (kept & (1u << (b * 4 + 3))) o3 |= __ldg(base + (b * 4 + 3) * 32);
                }
                remv |= (o0 | o1) | (o2 | o3);
            }
        }
    }
    if (lane == 0) g_nk[img] = nk;
}

// ---------------- kernel 5: parallel output writes ----------------
#define K5_PARTS 4
#define K5_SLICE ((MAXDET + K5_PARTS - 1) / K5_PARTS)   // 75

__global__ void __launch_bounds__(512) k5_out(const float* __restrict__ logits,
                                              float* __restrict__ out) {
    int img = blockIdx.y;
    int part = blockIdx.x;
    int tid = threadIdx.x;
    int nk = g_nk[img];
    int s0 = part * K5_SLICE;

    float* det = out;
    float* val = out + NB * MAXDET * 6;
    float* lg  = out + NB * MAXDET * 6 + NB * MAXDET;

    for (int t = tid; t < K5_SLICE * 6; t += 512) {
        int s = s0 + t / 6, c = t % 6;
        if (s >= MAXDET) break;
        float vv = 0.0f;
        if (s < nk) {
            int i  = g_keep[img * MAXDET + s];
            int gi = img * TOPK + i;
            if (c < 4)       vv = g_rawbox[gi * 4 + c];
            else if (c == 4) vv = g_selscore[gi];
            else             vv = (float)g_selcls[gi];
        }
        det[(img * MAXDET + s) * 6 + c] = vv;
    }
    for (int t = tid; t < K5_SLICE; t += 512) {
        int s = s0 + t;
        if (s >= MAXDET) break;
        val[img * MAXDET + s] = (s < nk) ? 1.0f : 0.0f;
    }
    for (int t = tid; t < K5_SLICE * NCLS; t += 512) {
        int s = s0 + t / NCLS, c = t % NCLS;
        if (s >= MAXDET) break;
        float vv = 0.0f;
        if (s < nk) {
            int aidx = g_selidx[img * TOPK + g_keep[img * MAXDET + s]];
            vv = __ldg(logits + ((size_t)(img * NQ + aidx)) * NCLS + c);
        }
        lg[(img * MAXDET + s) * NCLS + c] = vv;
    }
}

// ---------------- launch ----------------
extern "C" void kernel_launch(void* const* d_in, const int* in_sizes, int n_in,
                              void* d_out, int out_size) {
    const float* pred   = (const float*)d_in[0];
    const float* logits = (const float*)d_in[1];
    float* out = (float*)d_out;

    static bool attr_done = false;
    if (!attr_done) {
        cudaFuncSetAttribute(k1_score, cudaFuncAttributeMaxDynamicSharedMemorySize, K1_SMEM);
        cudaFuncSetAttribute(k2_select, cudaFuncAttributeMaxDynamicSharedMemorySize, K2_SMEM);
        attr_done = true;
    }

    k1_score<<<dim3(K1B, NB), 256, K1_SMEM>>>(pred);
    k2_select<<<NB, 1024, K2_SMEM>>>(pred);
    k3_mask<<<dim3(K3_BLKS, NB), 256>>>();
    k4_resolve<<<NB, 32>>>();
    k5_out<<<dim3(K5_PARTS, NB), 512>>>(logits, out);
}

// round 16
// speedup vs baseline: 1.7843x; 1.7843x over previous
#include <cuda_runtime.h>
#include <cstdint>
#include <cstddef>

#define NQ   25200
#define NB   16
#define NCLS 80
#define PC   85
#define TOPK 1024
#define MAXDET 300
#define CONF_THF 0.6f
#define IOU_THF  0.45f
#define MAX_WHF  4096.0f
#define CAND_CAP 2048
#define LISTCAP  16384
#define FULLM 0xffffffffu

// ---------------- scratch (device globals: no allocation allowed) ----------------
__device__ int      g_cls[NB * NQ];
__device__ unsigned long long g_list[NB * LISTCAP];
__device__ int      g_cnt[NB];                 // static-init zero; k2 resets after reading
__device__ int      g_selidx[NB * TOPK];
__device__ float    g_selscore[NB * TOPK];
__device__ int      g_selcls[NB * TOPK];
__device__ float    g_obox[NB * TOPK * 4];
__device__ float    g_area[NB * TOPK];
__device__ float    g_rawbox[NB * TOPK * 4];
__device__ unsigned g_mask[NB * TOPK * 32];

// ---------------- kernel 1: obj-gated warp-cooperative score/argmax ----------------
// Warp handles 32 anchors: lane reads obj of its anchor; only valid (obj>0.6)
// anchors get their 80 cls values read (coalesced within-row). 60% of rows skipped.
__global__ void __launch_bounds__(256) k1_score(const float* __restrict__ pred) {
    int img  = blockIdx.y;
    int warp = threadIdx.x >> 5;
    int lane = threadIdx.x & 31;
    int base = blockIdx.x * 256 + warp * 32;       // chunk of 32 anchors
    if (base >= NQ) return;                        // warp-uniform

    const float* ibase = pred + (size_t)img * NQ * PC;
    int a = base + lane;
    bool act = a < NQ;
    float obj = act ? __ldg(ibase + (size_t)a * PC + 4) : 0.0f;
    unsigned vmask = __ballot_sync(FULLM, act && (obj > CONF_THF));

    int cnt = 0;
    unsigned my_ord = 0; int my_idx = 0; int my_cls = 0;

    unsigned rem = vmask;
    while (rem) {
        int b = __ffs(rem) - 1; rem &= rem - 1;
        int aa = base + b;
        float objb = __shfl_sync(FULLM, obj, b);
        const float* cr = ibase + (size_t)aa * PC + 5;
        // lane covers cols {lane, lane+32, lane+64(<16)} — in-thread ascending order
        float best = __fmul_rn(__ldg(cr + lane), objb);
        int   bi   = lane;
        float p1 = __fmul_rn(__ldg(cr + 32 + lane), objb);
        if (p1 > best) { best = p1; bi = lane + 32; }
        if (lane < 16) {
            float p2 = __fmul_rn(__ldg(cr + 64 + lane), objb);
            if (p2 > best) { best = p2; bi = lane + 64; }
        }
        // butterfly reduce: max value, lowest index on ties (jnp.argmax semantics)
        #pragma unroll
        for (int off = 16; off; off >>= 1) {
            float ov = __shfl_xor_sync(FULLM, best, off);
            int   oi = __shfl_xor_sync(FULLM, bi, off);
            if (ov > best || (ov == best && oi < bi)) { best = ov; bi = oi; }
        }
        bool pass = best > CONF_THF;               // uniform across warp
        if (pass) {
            if (lane == cnt) {
                my_ord = __float_as_uint(best) | 0x80000000u;  // f2ord of positive float
                my_idx = aa;
                my_cls = bi;
            }
            cnt++;
        }
    }

    int pos0 = 0;
    if (lane == 0 && cnt) pos0 = atomicAdd(&g_cnt[img], cnt);
    pos0 = __shfl_sync(FULLM, pos0, 0);
    if (lane < cnt) {
        int pos = pos0 + lane;
        if (pos < LISTCAP)
            g_list[img * LISTCAP + pos] =
                ((unsigned long long)my_ord << 32) | (unsigned)my_idx;
        g_cls[img * NQ + my_idx] = my_cls;
    }
}

// ---------------- kernel 2: list-based radix-select top-1024 + hybrid sort + gather ----------------
#define K2_SMEM (LISTCAP * 8 + CAND_CAP * 8)
#define K2_ROUNDS (LISTCAP / 1024)

__device__ __forceinline__ void wstage(unsigned long long& v, int lane, unsigned idx,
                                       unsigned kk2, unsigned jj) {
    unsigned long long o = __shfl_xor_sync(FULLM, v, jj);
    bool low = ((lane & jj) == 0);
    bool up  = ((idx & kk2) == 0);
    unsigned long long mn = (v < o) ? v : o;
    unsigned long long mx = (v < o) ? o : v;
    v = (low == up) ? mn : mx;
}

__global__ void __launch_bounds__(1024) k2_select(const float* __restrict__ pred) {
    extern __shared__ unsigned char k2smem[];
    unsigned long long* s_list = (unsigned long long*)k2smem;
    unsigned long long* s_key  = (unsigned long long*)(k2smem + LISTCAP * 8);

    __shared__ unsigned s_hist[256];
    __shared__ unsigned s_sel, s_kk;
    __shared__ int s_cnt;

    int img = blockIdx.x;
    int tid = threadIdx.x;
    int lane = tid & 31;

    int n = g_cnt[img];
    if (n > LISTCAP) n = LISTCAP;
    for (int i = tid; i < n; i += 1024) s_list[i] = g_list[img * LISTCAP + i];
    __syncthreads();
    if (tid == 0) g_cnt[img] = 0;          // self-reset: no memset node needed

    unsigned T = 0;
    if (n > TOPK) {
        unsigned prefix = 0;
        int k = TOPK;
        for (int p = 0; p < 4; ++p) {
            int shift = 24 - 8 * p;
            unsigned fmask = (p == 0) ? 0u : (0xFFFFFFFFu << (32 - 8 * p));
            if (tid < 256) s_hist[tid] = 0;
            __syncthreads();
            #pragma unroll
            for (int r = 0; r < K2_ROUNDS; ++r) {
                int i = tid + (r << 10);
                bool act = i < n;
                unsigned o = act ? (unsigned)(s_list[i] >> 32) : 0u;
                bool in = act && (((o ^ prefix) & fmask) == 0);
                unsigned bin = (o >> shift) & 255u;
                unsigned mm = __ballot_sync(FULLM, in);
                if (in) {
                    unsigned same = __match_any_sync(mm, bin);
                    if ((__ffs(same) - 1) == lane)
                        atomicAdd(&s_hist[bin], __popc(same));
                }
            }
            __syncthreads();
            if (tid < 32) {
                unsigned c[8]; unsigned tot = 0;
                #pragma unroll
                for (int r = 0; r < 8; ++r) { c[r] = s_hist[tid * 8 + r]; tot += c[r]; }
                unsigned x = tot;
                #pragma unroll
                for (int off = 1; off < 32; off <<= 1) {
                    unsigned y = __shfl_down_sync(FULLM, x, off);
                    if (tid + off < 32) x += y;
                }
                unsigned acc = x - tot;
                #pragma unroll
                for (int r = 7; r >= 0; --r) {
                    unsigned inc = acc + c[r];
                    if ((int)inc >= k && (int)acc < k) { s_sel = (unsigned)(tid * 8 + r); s_kk = (unsigned)(k - (int)acc); }
                    acc = inc;
                }
            }
            __syncthreads();
            prefix |= s_sel << shift;
            k = (int)s_kk;
            __syncthreads();
        }
        T = prefix;
    }

    if (tid == 0) s_cnt = 0;
    __syncthreads();
    #pragma unroll
    for (int r = 0; r < K2_ROUNDS; ++r) {
        int i = tid + (r << 10);
        bool act = i < n;
        unsigned o = 0, idx = 0;
        if (act) {
            unsigned long long e = s_list[i];
            o = (unsigned)(e >> 32);
            idx = (unsigned)(e & 0xFFFFFFFFull);
        }
        bool take = act && (o >= T);
        unsigned mm = __ballot_sync(FULLM, take);
        if (mm) {
            int leader = __ffs(mm) - 1;
            int base = 0;
            if (lane == leader) base = atomicAdd(&s_cnt, __popc(mm));
            base = __shfl_sync(FULLM, base, leader);
            if (take) {
                int pos = base + __popc(mm & ((1u << lane) - 1u));
                if (pos < CAND_CAP)
                    s_key[pos] = ((unsigned long long)(~o) << 32) | idx;
            }
        }
    }
    __syncthreads();
    int nc = s_cnt; if (nc > CAND_CAP) nc = CAND_CAP;
    for (int i = nc + tid; i < CAND_CAP; i += 1024) s_key[i] = ~0ull;
    __syncthreads();

    {
        int W = tid >> 5;
        unsigned ia = W * 64 + lane;
        unsigned ib = W * 64 + 32 + lane;
        {
            unsigned long long a = s_key[ia], b = s_key[ib];
            #pragma unroll
            for (unsigned kk2 = 2; kk2 <= 32; kk2 <<= 1)
                #pragma unroll
                for (unsigned jj = kk2 >> 1; jj >= 1; jj >>= 1) {
                    wstage(a, lane, ia, kk2, jj);
                    wstage(b, lane, ib, kk2, jj);
                }
            s_key[ia] = a; s_key[ib] = b;
        }
        __syncthreads();
        for (unsigned kk2 = 64; kk2 <= CAND_CAP; kk2 <<= 1) {
            for (unsigned jj = kk2 >> 1; jj >= 32; jj >>= 1) {
                unsigned t = (unsigned)tid;
                unsigned e = ((t & ~(jj - 1)) << 1) | (t & (jj - 1));
                unsigned pi = e | jj;
                bool up = ((e & kk2) == 0);
                unsigned long long a = s_key[e], b2 = s_key[pi];
                bool sw = up ? (a > b2) : (a < b2);
                if (sw) { s_key[e] = b2; s_key[pi] = a; }
                __syncthreads();
            }
            unsigned long long a = s_key[ia], b = s_key[ib];
            #pragma unroll
            for (unsigned jj = 16; jj >= 1; jj >>= 1) {
                wstage(a, lane, ia, kk2, jj);
                wstage(b, lane, ib, kk2, jj);
            }
            s_key[ia] = a; s_key[ib] = b;
            __syncthreads();
        }
    }

    unsigned long long key = s_key[tid];
    int aidx; float scr; int cls;
    if ((key >> 32) == 0xFFFFFFFFull) {
        aidx = 0; scr = -1.0f; cls = 0;
    } else {
        aidx = (int)(unsigned)(key & 0xFFFFFFFFull);
        unsigned ordv = ~(unsigned)(key >> 32);
        scr  = __uint_as_float(ordv & 0x7FFFFFFFu);
        cls  = g_cls[img * NQ + aidx];
    }
    const float* row = pred + ((size_t)(img * NQ + aidx)) * PC;
    float cx = row[0], cy = row[1], w = row[2], h = row[3];
    float hw = __fmul_rn(w, 0.5f), hh = __fmul_rn(h, 0.5f);
    float x1 = __fsub_rn(cx, hw), y1 = __fsub_rn(cy, hh);
    float x2 = __fadd_rn(cx, hw), y2 = __fadd_rn(cy, hh);
    float off = __fmul_rn((float)cls, MAX_WHF);
    float ox1 = __fadd_rn(x1, off), oy1 = __fadd_rn(y1, off);
    float ox2 = __fadd_rn(x2, off), oy2 = __fadd_rn(y2, off);

    int gi = img * TOPK + tid;
    g_selidx[gi]   = aidx;
    g_selscore[gi] = scr;
    g_selcls[gi]   = cls;
    g_rawbox[gi*4+0] = x1; g_rawbox[gi*4+1] = y1; g_rawbox[gi*4+2] = x2; g_rawbox[gi*4+3] = y2;
    g_obox[gi*4+0] = ox1; g_obox[gi*4+1] = oy1; g_obox[gi*4+2] = ox2; g_obox[gi*4+3] = oy2;
    g_area[gi] = __fmul_rn(__fsub_rn(ox2, ox1), __fsub_rn(oy2, oy1));
}

// ---------------- kernel 3: IoU bitmask, warp-per-row, lane=j, div only if inter>0 ----------------
#define K3_BLKS 32

__global__ void __launch_bounds__(256) k3_mask() {
    int img = blockIdx.y;
    __shared__ float s_x1[TOPK], s_y1[TOPK], s_x2[TOPK], s_y2[TOPK], s_ar[TOPK];
    int tid = threadIdx.x;
    int wid = tid >> 5;
    int lane = tid & 31;
    for (int j = tid; j < TOPK; j += 256) {
        float4 b = ((const float4*)g_obox)[img * TOPK + j];
        s_x1[j] = b.x; s_y1[j] = b.y; s_x2[j] = b.z; s_y2[j] = b.w;
        s_ar[j] = g_area[img * TOPK + j];
    }
    __syncthreads();

    int g = blockIdx.x * 8 + wid;
    for (int rr = 0; rr < TOPK / (K3_BLKS * 8); ++rr) {
        int i = g + rr * (K3_BLKS * 8);
        float ax1 = s_x1[i], ay1 = s_y1[i], ax2 = s_x2[i], ay2 = s_y2[i], aar = s_ar[i];
        int w0 = i >> 5;
        unsigned* mrow = g_mask + (img * TOPK + i) * 32;
        if (lane < w0) mrow[lane] = 0;
        for (int w = w0; w < 32; ++w) {
            int j = w * 32 + lane;
            float xx1 = fmaxf(ax1, s_x1[j]);
            float yy1 = fmaxf(ay1, s_y1[j]);
            float xx2 = fminf(ax2, s_x2[j]);
            float yy2 = fminf(ay2, s_y2[j]);
            float iw = fmaxf(__fsub_rn(xx2, xx1), 0.0f);
            float ih = fmaxf(__fsub_rn(yy2, yy1), 0.0f);
            float inter = __fmul_rn(iw, ih);
            bool sup = false;
            if (j > i && inter > 0.0f) {
                float denom = __fadd_rn(__fsub_rn(__fadd_rn(aar, s_ar[j]), inter), 1e-9f);
                sup = __fdiv_rn(inter, denom) > IOU_THF;
            }
            unsigned bits = __ballot_sync(FULLM, sup);
            if (lane == 0) mrow[w] = bits;
        }
    }
}

// ---------------- kernel 4: word-parallel greedy resolve (smem) + write outputs ----------------
__global__ void __launch_bounds__(1024) k4_out(const float* __restrict__ logits,
                                               float* __restrict__ out) {
    extern __shared__ unsigned s_mask[];  // TOPK*32 words = 128 KB
    __shared__ int s_keep[MAXDET];
    __shared__ unsigned s_valid[32];
    __shared__ int s_nk;
    int img = blockIdx.x;
    int tid = threadIdx.x;
    int lane = tid & 31;

    {
        const uint4* gm = (const uint4*)(g_mask + img * TOPK * 32);
        uint4* sm4 = (uint4*)s_mask;
        #pragma unroll
        for (int kk = 0; kk < 8; ++kk) {
            int t = tid + (kk << 10);
            sm4[t] = __ldg(gm + t);
        }
    }
    {
        bool v = g_selscore[img * TOPK + tid] > CONF_THF;
        unsigned bal = __ballot_sync(FULLM, v);
        if (lane == 0) s_valid[tid >> 5] = bal;
    }
    __syncthreads();

    if (tid < 32) {
        unsigned remv = 0;
        int nk = 0;
        unsigned above = (lane < 31) ? ~((2u << lane) - 1u) : 0u;
        for (int w = 0; w < 32 && nk < MAXDET; ++w) {
            unsigned cur = s_valid[w] & ~__shfl_sync(FULLM, remv, w);
            unsigned kept = 0;
            if (cur) {
                unsigned diag = s_mask[(w * 32 + lane) * 32 + w];
                unsigned alive = cur;
                while (alive) {
                    bool supp = ((alive >> lane) & 1u) && ((diag & alive & above) != 0u);
                    unsigned sball = __ballot_sync(FULLM, supp);
                    if (!sball) { kept |= alive; break; }
                    int b = __ffs(sball) - 1;
                    unsigned ble = (b < 31) ? ((2u << b) - 1u) : 0xFFFFFFFFu;
                    unsigned batch = alive & ble;
                    kept |= batch;
                    alive &= ~batch;
                    alive &= ~__shfl_sync(FULLM, diag, b);
                }
                int cnt = __popc(kept);
                int room = MAXDET - nk;
                while (cnt > room) { kept &= ~(1u << (31 - __clz(kept))); --cnt; }
                if ((kept >> lane) & 1u)
                    s_keep[nk + __popc(kept & ((1u << lane) - 1u))] = w * 32 + lane;
                nk += cnt;
                if (kept) {
                    const unsigned* base = s_mask + (w * 32) * 32 + lane;
                    unsigned o0 = 0, o1 = 0, o2 = 0, o3 = 0;
                    #pragma unroll
                    for (int b = 0; b < 8; ++b) {
                        if (kept & (1u << (b * 4 + 0))) o0 |= base[(b * 4 + 0) * 32];
                        if (kept & (1u << (b * 4 + 1))) o1 |= base[(b * 4 + 1) * 32];
                        if (kept & (1u << (b * 4 + 2))) o2 |= base[(b * 4 + 2) * 32];
                        if (kept & (1u << (b * 4 + 3))) o3 |= base[(b * 4 + 3) * 32];
                    }
                    remv |= (o0 | o1) | (o2 | o3);
                }
            }
        }
        if (tid == 0) s_nk = nk;
    }
    __syncthreads();
    int nk = s_nk;

    float* det = out;                                  // (16,300,6)
    float* val = out + NB * MAXDET * 6;                // (16,300)
    float* lg  = out + NB * MAXDET * 6 + NB * MAXDET;  // (16,300,80)

    for (int t = tid; t < MAXDET * 6; t += 1024) {
        int s = t / 6, c = t % 6;
        float vv = 0.0f;
        if (s < nk) {
            int i  = s_keep[s];
            int gi = img * TOPK + i;
            if (c < 4)       vv = g_rawbox[gi * 4 + c];
            else if (c == 4) vv = g_selscore[gi];
            else             vv = (float)g_selcls[gi];
        }
        det[(img * MAXDET + s) * 6 + c] = vv;
    }
    for (int s = tid; s < MAXDET; s += 1024)
        val[img * MAXDET + s] = (s < nk) ? 1.0f : 0.0f;
    for (int t = tid; t < MAXDET * NCLS; t += 1024) {
        int s = t / NCLS, c = t % NCLS;
        float vv = 0.0f;
        if (s < nk) {
            int i = s_keep[s];
            int aidx = g_selidx[img * TOPK + i];
            vv = __ldg(logits + ((size_t)(img * NQ + aidx)) * NCLS + c);
        }
        lg[(img * MAXDET + s) * NCLS + c] = vv;
    }
}

// ---------------- launch ----------------
extern "C" void kernel_launch(void* const* d_in, const int* in_sizes, int n_in,
                              void* d_out, int out_size) {
    const float* pred   = (const float*)d_in[0];
    const float* logits = (const float*)d_in[1];
    float* out = (float*)d_out;

    static bool attr_done = false;
    if (!attr_done) {
        cudaFuncSetAttribute(k2_select, cudaFuncAttributeMaxDynamicSharedMemorySize, K2_SMEM);
        cudaFuncSetAttribute(k4_out, cudaFuncAttributeMaxDynamicSharedMemorySize, TOPK * 32 * 4);
        attr_done = true;
    }

    k1_score<<<dim3(99, NB), 256>>>(pred);
    k2_select<<<NB, 1024, K2_SMEM>>>(pred);
    k3_mask<<<dim3(K3_BLKS, NB), 256>>>();
    k4_out<<<NB, 1024, TOPK * 32 * 4>>>(logits, out);
}